// round 13
// baseline (speedup 1.0000x reference)
#include <cuda_runtime.h>
#include <cuda_bf16.h>

#define N_NODES 384
#define HEIGHT  60
#define CCH     128
#define N_LAYERS 4
#define NODE_SZ (CCH * HEIGHT)          // 7680 floats per node
// smem: lin [0, NODE_SZ) | FH [NODE_SZ, +4096u) | FL next. es_all aliases FH.
#define DYN_SMEM ((NODE_SZ + 8192) * 4)   // 62 KB -> 2 CTAs/SM

// ---------------- device scratch ----------------
// DOUBLE-BUFFERED: fused launch l reads buf l&1, writes buf (l+1)&1
__device__ __align__(16) float g_y[2][N_NODES * 2 * NODE_SZ];
// A fragments (bf16 hi/lo): [l][mt16][ks8][lane32][4regs] u32
__device__ __align__(16) unsigned WFh[N_LAYERS * 16384];
__device__ __align__(16) unsigned WFl[N_LAYERS * 16384];
__device__ float g_M[N_LAYERS * CCH * 6];
__device__ int   g_nbr[N_NODES * 16];
__device__ int   g_deg[N_NODES];
__device__ int   g_notok[N_LAYERS];     // 0 => ln_g==1 && ln_b==0 (fast path)

// ---------------- helpers ----------------
__device__ __forceinline__ unsigned pack_bf16x2(float a, float b) {
    __nv_bfloat162 p = __floats2bfloat162_rn(a, b);
    return *reinterpret_cast<unsigned*>(&p);
}
__device__ __forceinline__ void mma16816(float* d, const uint4& a, const uint2& b) {
    asm volatile(
        "mma.sync.aligned.m16n8k16.row.col.f32.bf16.bf16.f32 "
        "{%0,%1,%2,%3}, {%4,%5,%6,%7}, {%8,%9}, {%0,%1,%2,%3};"
        : "+f"(d[0]), "+f"(d[1]), "+f"(d[2]), "+f"(d[3])
        : "r"(a.x), "r"(a.y), "r"(a.z), "r"(a.w), "r"(b.x), "r"(b.y));
}

// linear (c,h) smem buffer -> B fragments (hi/lo) in smem.
__device__ __forceinline__ void frag_convert(const float* lin, unsigned* FH, unsigned* FL, int tid) {
    for (int s = tid; s < 4096; s += 512) {
        int breg = s & 1, lane = (s >> 1) & 31, nf = (s >> 6) & 7, ks = s >> 9;
        int c0 = ks * 16 + breg * 8 + (lane & 3) * 2;
        int h = nf * 8 + (lane >> 2);
        float v0 = 0.f, v1 = 0.f;
        if (h < HEIGHT) {
            v0 = lin[c0 * HEIGHT + h];
            v1 = lin[(c0 + 1) * HEIGHT + h];
        }
        float h0 = __bfloat162float(__float2bfloat16(v0));
        float h1 = __bfloat162float(__float2bfloat16(v1));
        FH[s] = pack_bf16x2(h0, h1);
        FL[s] = pack_bf16x2(v0 - h0, v1 - h1);
    }
}

// full-node MMA: 16 warps x 1 mtile; B frags from smem, A frags from global (L1).
__device__ __forceinline__ void mma_node(const unsigned* FH, const unsigned* FL,
                                         int l, int node, int tid,
                                         float* __restrict__ yout) {
    int w = tid >> 5, lane = tid & 31;
    int g = lane >> 2, t = lane & 3;
    const uint4* WAh = reinterpret_cast<const uint4*>(WFh);
    const uint4* WAl = reinterpret_cast<const uint4*>(WFl);

#pragma unroll
    for (int half = 0; half < 2; half++) {
        float acc[4][4];
#pragma unroll
        for (int nf = 0; nf < 4; nf++)
#pragma unroll
            for (int q = 0; q < 4; q++) acc[nf][q] = 0.f;

#pragma unroll
        for (int ks = 0; ks < 8; ks++) {
            int ai = ((l * 16 + w) * 8 + ks) * 32 + lane;
            uint4 Ah = __ldg(WAh + ai);
            uint4 Al = __ldg(WAl + ai);
#pragma unroll
            for (int nf = 0; nf < 4; nf++) {
                int s = ks * 512 + (half * 4 + nf) * 64 + lane * 2;
                uint2 Bh = *reinterpret_cast<const uint2*>(FH + s);
                uint2 Bl = *reinterpret_cast<const uint2*>(FL + s);
                mma16816(acc[nf], Ah, Bh);
                mma16816(acc[nf], Ah, Bl);
                mma16816(acc[nf], Al, Bh);
            }
        }
#pragma unroll
        for (int nf = 0; nf < 4; nf++) {
            int m = w * 16 + g;
            int h0 = (half * 4 + nf) * 8 + 2 * t;
            if (h0 < HEIGHT) {
                size_t base = ((size_t)node * 2 + (m >> 7)) * NODE_SZ;
                float* p0 = yout + base + (m & 127) * HEIGHT + h0;
                *(float2*)p0 = make_float2(acc[nf][0], acc[nf][1]);
                float* p1 = yout + base + ((m + 8) & 127) * HEIGHT + h0;
                *(float2*)p1 = make_float2(acc[nf][2], acc[nf][3]);
            }
        }
    }
}

// ---------------- setup: blk0..3 weights; blk4.. = per-node CSR ---------------
__global__ void setup_kernel(const int* __restrict__ ei, int E,
                             const float* __restrict__ conv_w,
                             const float* __restrict__ edge_w,
                             const float* __restrict__ edge_b,
                             const float* __restrict__ lng,
                             const float* __restrict__ lnb) {
    int tid = threadIdx.x;
    if (blockIdx.x >= 4) {
        // per-node CSR: find incoming edges, deterministic order (sorted by e)
        __shared__ int cnt;
        __shared__ int buf[16];
        int n = blockIdx.x - 4;
        if (tid == 0) cnt = 0;
        __syncthreads();
        const int* dst = ei + E;
        for (int e = tid; e < E; e += 384) {
            if (dst[e] == n) {
                int p = atomicAdd(&cnt, 1);
                if (p < 16) buf[p] = e;
            }
        }
        __syncthreads();
        if (tid == 0) {
            int c = cnt < 16 ? cnt : 16;
            for (int a = 1; a < c; a++) {           // insertion sort by e
                int v = buf[a], b = a - 1;
                while (b >= 0 && buf[b] > v) { buf[b + 1] = buf[b]; b--; }
                buf[b + 1] = v;
            }
            int cc = c < 8 ? c : 8;
            g_deg[n] = cc;
            for (int a = 0; a < cc; a++) g_nbr[n * 16 + a] = buf[a];
        }
        return;
    }
    int l = blockIdx.x;
    const float* cw = conv_w + l * (CCH * 3 * CCH);
    for (int i = tid; i < 16384; i += 384) {
        int j = i & 3, lane = (i >> 2) & 31, ks = (i >> 7) & 7, mt = i >> 10;
        int g = lane >> 2, t = lane & 3;
        int m = (mt << 4) + g + ((j & 1) << 3);
        int k = (ks << 4) + (t << 1) + ((j >> 1) << 3);
        float v0, v1;
        if (m < 128) {
            v0 = cw[m * 384 + k] - cw[m * 384 + 128 + k];
            v1 = cw[m * 384 + k + 1] - cw[m * 384 + 128 + k + 1];
        } else {
            v0 = cw[(m - 128) * 384 + 128 + k];
            v1 = cw[(m - 128) * 384 + 128 + k + 1];
        }
        float h0 = __bfloat162float(__float2bfloat16(v0));
        float h1 = __bfloat162float(__float2bfloat16(v1));
        WFh[l * 16384 + i] = pack_bf16x2(h0, h1);
        WFl[l * 16384 + i] = pack_bf16x2(v0 - h0, v1 - h1);
    }
    // LN trivial-params check
    {
        const float* gl = lng + l * NODE_SZ;
        const float* bl = lnb + l * NODE_SZ;
        int bad = 0;
        for (int i = tid; i < NODE_SZ; i += 384)
            bad |= (gl[i] != 1.f) | (bl[i] != 0.f);
        if (bad) atomicOr(&g_notok[l], 1);
    }
    if (tid < CCH) {
        int c = tid;
        const float* cw3 = cw + c * 384 + 256;
        const float* ewl = edge_w + l * (CCH * 5);
        const float* ebl = edge_b + l * CCH;
        float m0 = 0.f, m1 = 0.f, m2 = 0.f, m3 = 0.f, m4 = 0.f, m5 = 0.f;
        for (int k = 0; k < CCH; k++) {
            float w = cw3[k];
            m0 += w * ewl[k * 5 + 0];
            m1 += w * ewl[k * 5 + 1];
            m2 += w * ewl[k * 5 + 2];
            m3 += w * ewl[k * 5 + 3];
            m4 += w * ewl[k * 5 + 4];
            m5 += w * ebl[k];
        }
        float* Mp = g_M + l * (CCH * 6) + c * 6;
        Mp[0] = m0; Mp[1] = m1; Mp[2] = m2; Mp[3] = m3; Mp[4] = m4; Mp[5] = m5;
    }
}

// ---------------- G0: layer-0 GEMM, smem-resident -> buf 0 --------------------
__global__ __launch_bounds__(512, 2)
void gemm0_kernel(const float* __restrict__ x0) {
    extern __shared__ float sm[];
    float* lin = sm;
    unsigned* FH = reinterpret_cast<unsigned*>(sm + NODE_SZ);
    unsigned* FL = FH + 4096;
    int node = blockIdx.x, tid = threadIdx.x;
    const float* xn = x0 + (size_t)node * NODE_SZ;
#pragma unroll
    for (int it = 0; it < 15; it++)
        lin[tid + (it << 9)] = xn[tid + (it << 9)];
    __syncthreads();
    frag_convert(lin, FH, FL, tid);
    __syncthreads();
    mma_node(FH, FL, 0, node, tid, g_y[0]);
}

// ---------------- F_l: edge(l) batched-stats [+ gemm(l+1) in-CTA] -------------
__global__ __launch_bounds__(512, 2)
void fused_kernel(const float* __restrict__ ea,
                  const float* __restrict__ lng,
                  const float* __restrict__ lnb,
                  const int* __restrict__ ei,
                  float* __restrict__ dout, int l) {
    extern __shared__ float sm[];
    float* lin = sm;                                         // [0, NODE_SZ)
    unsigned* FH = reinterpret_cast<unsigned*>(sm + NODE_SZ);
    unsigned* FL = FH + 4096;
    float* es_all = reinterpret_cast<float*>(FH);            // aliases FH (dead by MMA)
    __shared__ float red[8][32];                             // [j][s1 x16 | s2 x16]
    __shared__ float murs[16];                               // mu[j], rs[j]

    int n = blockIdx.x, tid = threadIdx.x;
    const float* ybuf = g_y[l & 1];
    int deg = g_deg[n];
    int notok = g_notok[l];
    int lane = tid & 31, wid = tid >> 5;

    // neighbor source node ids
    int srcs[8];
#pragma unroll
    for (int j = 0; j < 8; j++)
        srcs[j] = (j < deg) ? ei[g_nbr[n * 16 + j]] : 0;

    // edge scalars for all edges
    for (int idx = tid; idx < deg * CCH; idx += 512) {
        int j = idx >> 7, c = idx & 127;
        int e = g_nbr[n * 16 + j];
        const float* Mp = g_M + l * (CCH * 6) + c * 6;
        const float* eap = ea + e * 5;
        es_all[idx] = fmaf(Mp[0], eap[0], fmaf(Mp[1], eap[1], fmaf(Mp[2], eap[2],
                      fmaf(Mp[3], eap[3], fmaf(Mp[4], eap[4], Mp[5])))));
    }

    const float* yan = ybuf + (size_t)(2 * n) * NODE_SZ;
    float ya[15], acc[15];
#pragma unroll
    for (int it = 0; it < 15; it++) {
        ya[it] = __ldg(yan + tid + (it << 9));
        acc[it] = 0.f;
    }
    __syncthreads();   // es_all visible

    // ---- phase 1: stats for ALL edges in one streaming pass (no barriers) ----
    float s1[8], s2[8];
#pragma unroll
    for (int j = 0; j < 8; j++) { s1[j] = 0.f; s2[j] = 0.f; }
#pragma unroll
    for (int it = 0; it < 15; it++) {
        int i = tid + (it << 9);
        int c = i / HEIGHT;
        float base = ya[it];
#pragma unroll
        for (int j = 0; j < 8; j++) {
            if (j < deg) {
                float v = base + __ldg(ybuf + (size_t)(2 * srcs[j] + 1) * NODE_SZ + i)
                        + es_all[j * CCH + c];
                s1[j] += v;
                s2[j] = fmaf(v, v, s2[j]);
            }
        }
    }
#pragma unroll
    for (int j = 0; j < 8; j++) {
#pragma unroll
        for (int o = 16; o; o >>= 1) {
            s1[j] += __shfl_xor_sync(0xffffffffu, s1[j], o);
            s2[j] += __shfl_xor_sync(0xffffffffu, s2[j], o);
        }
        if (lane == 0 && j < deg) { red[j][wid] = s1[j]; red[j][16 + wid] = s2[j]; }
    }
    __syncthreads();
    // warps 0..7: warp j computes mu/rs for edge j
    if (wid < 8 && lane == 0 && wid < deg) {
        float a = 0.f, b2 = 0.f;
#pragma unroll
        for (int w = 0; w < 16; w++) { a += red[wid][w]; b2 += red[wid][16 + w]; }
        float mu = a * (1.f / (float)NODE_SZ);
        murs[2 * wid] = mu;
        murs[2 * wid + 1] = rsqrtf(b2 * (1.f / (float)NODE_SZ) - mu * mu + 1e-5f);
    }
    __syncthreads();

    // ---- phase 2: recompute v, normalize, relu, accumulate (no barriers) -----
    if (!notok) {
#pragma unroll
        for (int j = 0; j < 8; j++) {
            if (j < deg) {
                float mu = murs[2 * j], rs = murs[2 * j + 1];
                const float* yb = ybuf + (size_t)(2 * srcs[j] + 1) * NODE_SZ;
                const float* esj = es_all + j * CCH;
#pragma unroll
                for (int it = 0; it < 15; it++) {
                    int i = tid + (it << 9);
                    float v = ya[it] + __ldg(yb + i) + esj[i / HEIGHT];
                    acc[it] = fmaf(rs, fmaxf(v - mu, 0.f), acc[it]);
                }
            }
        }
    } else {
        const float* gl = lng + l * NODE_SZ;
        const float* bl = lnb + l * NODE_SZ;
#pragma unroll
        for (int j = 0; j < 8; j++) {
            if (j < deg) {
                float mu = murs[2 * j], rs = murs[2 * j + 1];
                const float* yb = ybuf + (size_t)(2 * srcs[j] + 1) * NODE_SZ;
                const float* esj = es_all + j * CCH;
#pragma unroll
                for (int it = 0; it < 15; it++) {
                    int i = tid + (it << 9);
                    float v = ya[it] + __ldg(yb + i) + esj[i / HEIGHT];
                    float o2 = (v - mu) * rs * __ldg(gl + i) + __ldg(bl + i);
                    acc[it] += fmaxf(o2, 0.f);
                }
            }
        }
    }

    if (l == 3) {
        float* on = dout + (size_t)n * NODE_SZ;
#pragma unroll
        for (int it = 0; it < 15; it++)
            on[tid + (it << 9)] = acc[it];
        return;
    }

    // ---- in-CTA gemm(l+1): acc -> lin -> B frags (smem) -> MMA -> buf (l+1)&1 -
    __syncthreads();              // es_all reads complete before FH overwrite
#pragma unroll
    for (int it = 0; it < 15; it++)
        lin[tid + (it << 9)] = acc[it];
    __syncthreads();
    frag_convert(lin, FH, FL, tid);
    __syncthreads();
    mma_node(FH, FL, l + 1, n, tid, g_y[(l + 1) & 1]);
}

// ---------------- launch -----------------------------------------------------
extern "C" void kernel_launch(void* const* d_in, const int* in_sizes, int n_in,
                              void* d_out, int out_size) {
    const float* x   = (const float*)d_in[0];
    const float* ea  = (const float*)d_in[1];
    const float* ew  = (const float*)d_in[2];
    const float* eb  = (const float*)d_in[3];
    const float* cw  = (const float*)d_in[4];
    const float* lng = (const float*)d_in[5];
    const float* lnb = (const float*)d_in[6];
    const int*   ei  = (const int*)d_in[7];
    float* out = (float*)d_out;
    int E = in_sizes[7] / 2;

    cudaFuncSetAttribute(gemm0_kernel, cudaFuncAttributeMaxDynamicSharedMemorySize, DYN_SMEM);
    cudaFuncSetAttribute(fused_kernel, cudaFuncAttributeMaxDynamicSharedMemorySize, DYN_SMEM);

    setup_kernel<<<4 + N_NODES, 384>>>(ei, E, cw, ew, eb, lng, lnb);
    gemm0_kernel<<<N_NODES, 512, DYN_SMEM>>>(x);
    for (int l = 0; l < N_LAYERS; l++)
        fused_kernel<<<N_NODES, 512, DYN_SMEM>>>(ea, lng, lnb, ei, out, l);
}

// round 14
// speedup vs baseline: 1.2600x; 1.2600x over previous
#include <cuda_runtime.h>
#include <cuda_bf16.h>

#define N_NODES 384
#define HEIGHT  60
#define CCH     128
#define N_LAYERS 4
#define NODE_SZ (CCH * HEIGHT)          // 7680 floats per node
#define DYN_SMEM ((NODE_SZ + 8192) * 4)   // 62 KB -> 2 CTAs/SM

// ---------------- device scratch ----------------
__device__ __align__(16) float g_y[2][N_NODES * 2 * NODE_SZ];
__device__ __align__(16) unsigned WFh[N_LAYERS * 16384];
__device__ __align__(16) unsigned WFl[N_LAYERS * 16384];
__device__ float g_M[N_LAYERS * CCH * 6];
__device__ int   g_nbr[N_NODES * 16];
__device__ int   g_deg[N_NODES];
__device__ int   g_notok[N_LAYERS];

// ---------------- helpers ----------------
__device__ __forceinline__ unsigned pack_bf16x2(float a, float b) {
    __nv_bfloat162 p = __floats2bfloat162_rn(a, b);
    return *reinterpret_cast<unsigned*>(&p);
}
__device__ __forceinline__ void mma16816(float* d, const uint4& a, const uint2& b) {
    asm volatile(
        "mma.sync.aligned.m16n8k16.row.col.f32.bf16.bf16.f32 "
        "{%0,%1,%2,%3}, {%4,%5,%6,%7}, {%8,%9}, {%0,%1,%2,%3};"
        : "+f"(d[0]), "+f"(d[1]), "+f"(d[2]), "+f"(d[3])
        : "r"(a.x), "r"(a.y), "r"(a.z), "r"(a.w), "r"(b.x), "r"(b.y));
}

__device__ __forceinline__ void frag_convert(const float* lin, unsigned* FH, unsigned* FL, int tid) {
    for (int s = tid; s < 4096; s += 512) {
        int breg = s & 1, lane = (s >> 1) & 31, nf = (s >> 6) & 7, ks = s >> 9;
        int c0 = ks * 16 + breg * 8 + (lane & 3) * 2;
        int h = nf * 8 + (lane >> 2);
        float v0 = 0.f, v1 = 0.f;
        if (h < HEIGHT) {
            v0 = lin[c0 * HEIGHT + h];
            v1 = lin[(c0 + 1) * HEIGHT + h];
        }
        float h0 = __bfloat162float(__float2bfloat16(v0));
        float h1 = __bfloat162float(__float2bfloat16(v1));
        FH[s] = pack_bf16x2(h0, h1);
        FL[s] = pack_bf16x2(v0 - h0, v1 - h1);
    }
}

__device__ __forceinline__ void mma_node(const unsigned* FH, const unsigned* FL,
                                         int l, int node, int tid,
                                         float* __restrict__ yout) {
    int w = tid >> 5, lane = tid & 31;
    int g = lane >> 2, t = lane & 3;
    const uint4* WAh = reinterpret_cast<const uint4*>(WFh);
    const uint4* WAl = reinterpret_cast<const uint4*>(WFl);

#pragma unroll
    for (int half = 0; half < 2; half++) {
        float acc[4][4];
#pragma unroll
        for (int nf = 0; nf < 4; nf++)
#pragma unroll
            for (int q = 0; q < 4; q++) acc[nf][q] = 0.f;

#pragma unroll
        for (int ks = 0; ks < 8; ks++) {
            int ai = ((l * 16 + w) * 8 + ks) * 32 + lane;
            uint4 Ah = __ldg(WAh + ai);
            uint4 Al = __ldg(WAl + ai);
#pragma unroll
            for (int nf = 0; nf < 4; nf++) {
                int s = ks * 512 + (half * 4 + nf) * 64 + lane * 2;
                uint2 Bh = *reinterpret_cast<const uint2*>(FH + s);
                uint2 Bl = *reinterpret_cast<const uint2*>(FL + s);
                mma16816(acc[nf], Ah, Bh);
                mma16816(acc[nf], Ah, Bl);
                mma16816(acc[nf], Al, Bh);
            }
        }
#pragma unroll
        for (int nf = 0; nf < 4; nf++) {
            int m = w * 16 + g;
            int h0 = (half * 4 + nf) * 8 + 2 * t;
            if (h0 < HEIGHT) {
                size_t base = ((size_t)node * 2 + (m >> 7)) * NODE_SZ;
                float* p0 = yout + base + (m & 127) * HEIGHT + h0;
                *(float2*)p0 = make_float2(acc[nf][0], acc[nf][1]);
                float* p1 = yout + base + ((m + 8) & 127) * HEIGHT + h0;
                *(float2*)p1 = make_float2(acc[nf][2], acc[nf][3]);
            }
        }
    }
}

// ---------------- setup: blk0..3 weights; blk4.. = per-node CSR ---------------
__global__ void setup_kernel(const int* __restrict__ ei, int E,
                             const float* __restrict__ conv_w,
                             const float* __restrict__ edge_w,
                             const float* __restrict__ edge_b,
                             const float* __restrict__ lng,
                             const float* __restrict__ lnb) {
    int tid = threadIdx.x;
    if (blockIdx.x >= 4) {
        __shared__ int cnt;
        __shared__ int buf[16];
        int n = blockIdx.x - 4;
        if (tid == 0) cnt = 0;
        __syncthreads();
        const int* dst = ei + E;
        for (int e = tid; e < E; e += 384) {
            if (dst[e] == n) {
                int p = atomicAdd(&cnt, 1);
                if (p < 16) buf[p] = e;
            }
        }
        __syncthreads();
        if (tid == 0) {
            int c = cnt < 16 ? cnt : 16;
            for (int a = 1; a < c; a++) {
                int v = buf[a], b = a - 1;
                while (b >= 0 && buf[b] > v) { buf[b + 1] = buf[b]; b--; }
                buf[b + 1] = v;
            }
            int cc = c < 8 ? c : 8;
            g_deg[n] = cc;
            for (int a = 0; a < cc; a++) g_nbr[n * 16 + a] = buf[a];
        }
        return;
    }
    int l = blockIdx.x;
    const float* cw = conv_w + l * (CCH * 3 * CCH);
    for (int i = tid; i < 16384; i += 384) {
        int j = i & 3, lane = (i >> 2) & 31, ks = (i >> 7) & 7, mt = i >> 10;
        int g = lane >> 2, t = lane & 3;
        int m = (mt << 4) + g + ((j & 1) << 3);
        int k = (ks << 4) + (t << 1) + ((j >> 1) << 3);
        float v0, v1;
        if (m < 128) {
            v0 = cw[m * 384 + k] - cw[m * 384 + 128 + k];
            v1 = cw[m * 384 + k + 1] - cw[m * 384 + 128 + k + 1];
        } else {
            v0 = cw[(m - 128) * 384 + 128 + k];
            v1 = cw[(m - 128) * 384 + 128 + k + 1];
        }
        float h0 = __bfloat162float(__float2bfloat16(v0));
        float h1 = __bfloat162float(__float2bfloat16(v1));
        WFh[l * 16384 + i] = pack_bf16x2(h0, h1);
        WFl[l * 16384 + i] = pack_bf16x2(v0 - h0, v1 - h1);
    }
    {
        const float* gl = lng + l * NODE_SZ;
        const float* bl = lnb + l * NODE_SZ;
        int bad = 0;
        for (int i = tid; i < NODE_SZ; i += 384)
            bad |= (gl[i] != 1.f) | (bl[i] != 0.f);
        if (bad) atomicOr(&g_notok[l], 1);
    }
    if (tid < CCH) {
        int c = tid;
        const float* cw3 = cw + c * 384 + 256;
        const float* ewl = edge_w + l * (CCH * 5);
        const float* ebl = edge_b + l * CCH;
        float m0 = 0.f, m1 = 0.f, m2 = 0.f, m3 = 0.f, m4 = 0.f, m5 = 0.f;
        for (int k = 0; k < CCH; k++) {
            float w = cw3[k];
            m0 += w * ewl[k * 5 + 0];
            m1 += w * ewl[k * 5 + 1];
            m2 += w * ewl[k * 5 + 2];
            m3 += w * ewl[k * 5 + 3];
            m4 += w * ewl[k * 5 + 4];
            m5 += w * ebl[k];
        }
        float* Mp = g_M + l * (CCH * 6) + c * 6;
        Mp[0] = m0; Mp[1] = m1; Mp[2] = m2; Mp[3] = m3; Mp[4] = m4; Mp[5] = m5;
    }
}

// ---------------- G0: layer-0 GEMM, smem-resident -> buf 0 --------------------
__global__ __launch_bounds__(512, 2)
void gemm0_kernel(const float* __restrict__ x0) {
    extern __shared__ float sm[];
    float* lin = sm;
    unsigned* FH = reinterpret_cast<unsigned*>(sm + NODE_SZ);
    unsigned* FL = FH + 4096;
    int node = blockIdx.x, tid = threadIdx.x;
    const float* xn = x0 + (size_t)node * NODE_SZ;
#pragma unroll
    for (int it = 0; it < 15; it++)
        lin[tid + (it << 9)] = xn[tid + (it << 9)];
    __syncthreads();
    frag_convert(lin, FH, FL, tid);
    __syncthreads();
    mma_node(FH, FL, 0, node, tid, g_y[0]);
}

// ---------------- F_l: edge(l) [+ gemm(l+1) in-CTA] ---------------------------
__global__ __launch_bounds__(512, 2)
void fused_kernel(const float* __restrict__ ea,
                  const float* __restrict__ lng,
                  const float* __restrict__ lnb,
                  const int* __restrict__ ei,
                  float* __restrict__ dout, int l) {
    extern __shared__ float sm[];
    float* lin = sm;
    unsigned* FH = reinterpret_cast<unsigned*>(sm + NODE_SZ);
    unsigned* FL = FH + 4096;
    float* es_all = reinterpret_cast<float*>(FH);   // aliases FH (dead by MMA)
    __shared__ float red[8][32];
    __shared__ float murs[16];

    int n = blockIdx.x, tid = threadIdx.x;
    const float* ybuf = g_y[l & 1];
    int deg = g_deg[n];
    int notok = g_notok[l];
    int lane = tid & 31, wid = tid >> 5;

    for (int idx = tid; idx < deg * CCH; idx += 512) {
        int j = idx >> 7, c = idx & 127;
        int e = g_nbr[n * 16 + j];
        const float* Mp = g_M + l * (CCH * 6) + c * 6;
        const float* eap = ea + e * 5;
        es_all[idx] = fmaf(Mp[0], eap[0], fmaf(Mp[1], eap[1], fmaf(Mp[2], eap[2],
                      fmaf(Mp[3], eap[3], fmaf(Mp[4], eap[4], Mp[5])))));
    }

    const float* yan = ybuf + (size_t)(2 * n) * NODE_SZ;
    float ya[15], acc[15];
#pragma unroll
    for (int it = 0; it < 15; it++) {
        ya[it] = __ldg(yan + tid + (it << 9));
        acc[it] = 0.f;
    }
    __syncthreads();   // es_all visible

    if (deg == 6 && !notok) {
        // ======== FAST PATH: deg==6, trivial LN params ========
        const float* ybp[6];
#pragma unroll
        for (int j = 0; j < 6; j++)
            ybp[j] = ybuf + (size_t)(2 * ei[g_nbr[n * 16 + j]] + 1) * NODE_SZ;

        // phase 1: stats for all 6 edges, zero barriers, pipelined LDGs
        float s1[6], s2[6];
#pragma unroll
        for (int j = 0; j < 6; j++) { s1[j] = 0.f; s2[j] = 0.f; }
#pragma unroll
        for (int it = 0; it < 15; it++) {
            int i = tid + (it << 9);
            int c = i / HEIGHT;
            float base = ya[it];
#pragma unroll
            for (int j = 0; j < 6; j++) {
                float v = base + __ldg(ybp[j] + i) + es_all[j * CCH + c];
                s1[j] += v;
                s2[j] = fmaf(v, v, s2[j]);
            }
        }
#pragma unroll
        for (int j = 0; j < 6; j++) {
#pragma unroll
            for (int o = 16; o; o >>= 1) {
                s1[j] += __shfl_xor_sync(0xffffffffu, s1[j], o);
                s2[j] += __shfl_xor_sync(0xffffffffu, s2[j], o);
            }
            if (lane == 0) { red[j][wid] = s1[j]; red[j][16 + wid] = s2[j]; }
        }
        __syncthreads();
        if (wid < 6 && lane == 0) {
            float a = 0.f, b2 = 0.f;
#pragma unroll
            for (int w = 0; w < 16; w++) { a += red[wid][w]; b2 += red[wid][16 + w]; }
            float mu = a * (1.f / (float)NODE_SZ);
            murs[2 * wid] = mu;
            murs[2 * wid + 1] = rsqrtf(b2 * (1.f / (float)NODE_SZ) - mu * mu + 1e-5f);
        }
        __syncthreads();

        // phase 2: recompute v (L1/L2 hot), normalize, relu, accumulate
#pragma unroll
        for (int j = 0; j < 6; j++) {
            float mu = murs[2 * j], rs = murs[2 * j + 1];
            const float* yb = ybp[j];
            const float* esj = es_all + j * CCH;
#pragma unroll
            for (int it = 0; it < 15; it++) {
                int i = tid + (it << 9);
                float v = ya[it] + __ldg(yb + i) + esj[i / HEIGHT];
                acc[it] = fmaf(rs, fmaxf(v - mu, 0.f), acc[it]);
            }
        }
    } else {
        // ======== GENERIC PATH (R12): per-edge, full LN ========
        for (int j = 0; j < deg; j++) {
            int e = g_nbr[n * 16 + j];
            int s = ei[e];
            const float* yb = ybuf + (size_t)(2 * s + 1) * NODE_SZ;
            const float* esj = es_all + j * CCH;

            float t[15];
            float s1 = 0.f, s2 = 0.f;
#pragma unroll
            for (int it = 0; it < 15; it++) {
                int i = tid + (it << 9);
                float v = ya[it] + __ldg(yb + i) + esj[i / HEIGHT];
                t[it] = v;
                s1 += v;
                s2 += v * v;
            }
#pragma unroll
            for (int o = 16; o; o >>= 1) {
                s1 += __shfl_xor_sync(0xffffffffu, s1, o);
                s2 += __shfl_xor_sync(0xffffffffu, s2, o);
            }
            if (lane == 0) { red[j][wid] = s1; red[j][16 + wid] = s2; }
            __syncthreads();
            float a = 0.f, b2 = 0.f;
#pragma unroll
            for (int w = 0; w < 16; w++) { a += red[j][w]; b2 += red[j][16 + w]; }
            float mu = a * (1.f / (float)NODE_SZ);
            float rs = rsqrtf(b2 * (1.f / (float)NODE_SZ) - mu * mu + 1e-5f);
            if (!notok) {
#pragma unroll
                for (int it = 0; it < 15; it++)
                    acc[it] = fmaf(rs, fmaxf(t[it] - mu, 0.f), acc[it]);
            } else {
                const float* gl = lng + l * NODE_SZ;
                const float* bl = lnb + l * NODE_SZ;
#pragma unroll
                for (int it = 0; it < 15; it++) {
                    int i = tid + (it << 9);
                    float o2 = (t[it] - mu) * rs * __ldg(gl + i) + __ldg(bl + i);
                    acc[it] += fmaxf(o2, 0.f);
                }
            }
        }
    }

    if (l == 3) {
        float* on = dout + (size_t)n * NODE_SZ;
#pragma unroll
        for (int it = 0; it < 15; it++)
            on[tid + (it << 9)] = acc[it];
        return;
    }

    // ---- in-CTA gemm(l+1): acc -> lin -> B frags (smem) -> MMA -> buf (l+1)&1 -
    __syncthreads();              // es_all reads complete before FH overwrite
#pragma unroll
    for (int it = 0; it < 15; it++)
        lin[tid + (it << 9)] = acc[it];
    __syncthreads();
    frag_convert(lin, FH, FL, tid);
    __syncthreads();
    mma_node(FH, FL, l + 1, n, tid, g_y[(l + 1) & 1]);
}

// ---------------- launch -----------------------------------------------------
extern "C" void kernel_launch(void* const* d_in, const int* in_sizes, int n_in,
                              void* d_out, int out_size) {
    const float* x   = (const float*)d_in[0];
    const float* ea  = (const float*)d_in[1];
    const float* ew  = (const float*)d_in[2];
    const float* eb  = (const float*)d_in[3];
    const float* cw  = (const float*)d_in[4];
    const float* lng = (const float*)d_in[5];
    const float* lnb = (const float*)d_in[6];
    const int*   ei  = (const int*)d_in[7];
    float* out = (float*)d_out;
    int E = in_sizes[7] / 2;

    cudaFuncSetAttribute(gemm0_kernel, cudaFuncAttributeMaxDynamicSharedMemorySize, DYN_SMEM);
    cudaFuncSetAttribute(fused_kernel, cudaFuncAttributeMaxDynamicSharedMemorySize, DYN_SMEM);

    setup_kernel<<<4 + N_NODES, 384>>>(ei, E, cw, ew, eb, lng, lnb);
    gemm0_kernel<<<N_NODES, 512, DYN_SMEM>>>(x);
    for (int l = 0; l < N_LAYERS; l++)
        fused_kernel<<<N_NODES, 512, DYN_SMEM>>>(ea, lng, lnb, ei, out, l);
}

// round 15
// speedup vs baseline: 1.2693x; 1.0074x over previous
#include <cuda_runtime.h>
#include <cuda_bf16.h>

#define N_NODES 384
#define HEIGHT  60
#define PH      64                      // padded height
#define CCH     128
#define N_LAYERS 4
#define PNODE   (CCH * PH)              // 8192 padded floats per node part
#define DYN_SMEM ((PNODE + 8192) * 4)   // lin(32KB) + FH/FL(32KB) = 64KB -> 2 CTAs/SM

// ---------------- device scratch ----------------
// padded layout [c][h], h-stride 64; pads (h=60..63) never written -> stay 0
__device__ __align__(16) float g_y[2][N_NODES * 2 * PNODE];
__device__ __align__(16) unsigned WFh[N_LAYERS * 16384];
__device__ __align__(16) unsigned WFl[N_LAYERS * 16384];
__device__ float g_M[N_LAYERS * CCH * 6];
__device__ int   g_nbr[N_NODES * 16];
__device__ int   g_deg[N_NODES];
__device__ int   g_notok[N_LAYERS];

// ---------------- helpers ----------------
__device__ __forceinline__ unsigned pack_bf16x2(float a, float b) {
    __nv_bfloat162 p = __floats2bfloat162_rn(a, b);
    return *reinterpret_cast<unsigned*>(&p);
}
__device__ __forceinline__ void mma16816(float* d, const uint4& a, const uint2& b) {
    asm volatile(
        "mma.sync.aligned.m16n8k16.row.col.f32.bf16.bf16.f32 "
        "{%0,%1,%2,%3}, {%4,%5,%6,%7}, {%8,%9}, {%0,%1,%2,%3};"
        : "+f"(d[0]), "+f"(d[1]), "+f"(d[2]), "+f"(d[3])
        : "r"(a.x), "r"(a.y), "r"(a.z), "r"(a.w), "r"(b.x), "r"(b.y));
}

// padded-linear (c,h;stride 64) smem buffer -> B fragments (hi/lo) in smem.
__device__ __forceinline__ void frag_convert(const float* lin, unsigned* FH, unsigned* FL, int tid) {
    for (int s = tid; s < 4096; s += 512) {
        int breg = s & 1, lane = (s >> 1) & 31, nf = (s >> 6) & 7, ks = s >> 9;
        int c0 = ks * 16 + breg * 8 + (lane & 3) * 2;
        int h = nf * 8 + (lane >> 2);
        float v0 = 0.f, v1 = 0.f;
        if (h < HEIGHT) {
            v0 = lin[(c0 << 6) + h];
            v1 = lin[((c0 + 1) << 6) + h];
        }
        float h0 = __bfloat162float(__float2bfloat16(v0));
        float h1 = __bfloat162float(__float2bfloat16(v1));
        FH[s] = pack_bf16x2(h0, h1);
        FL[s] = pack_bf16x2(v0 - h0, v1 - h1);
    }
}

// full-node MMA -> padded g_y layout
__device__ __forceinline__ void mma_node(const unsigned* FH, const unsigned* FL,
                                         int l, int node, int tid,
                                         float* __restrict__ yout) {
    int w = tid >> 5, lane = tid & 31;
    int g = lane >> 2, t = lane & 3;
    const uint4* WAh = reinterpret_cast<const uint4*>(WFh);
    const uint4* WAl = reinterpret_cast<const uint4*>(WFl);

#pragma unroll
    for (int half = 0; half < 2; half++) {
        float acc[4][4];
#pragma unroll
        for (int nf = 0; nf < 4; nf++)
#pragma unroll
            for (int q = 0; q < 4; q++) acc[nf][q] = 0.f;

#pragma unroll
        for (int ks = 0; ks < 8; ks++) {
            int ai = ((l * 16 + w) * 8 + ks) * 32 + lane;
            uint4 Ah = __ldg(WAh + ai);
            uint4 Al = __ldg(WAl + ai);
#pragma unroll
            for (int nf = 0; nf < 4; nf++) {
                int s = ks * 512 + (half * 4 + nf) * 64 + lane * 2;
                uint2 Bh = *reinterpret_cast<const uint2*>(FH + s);
                uint2 Bl = *reinterpret_cast<const uint2*>(FL + s);
                mma16816(acc[nf], Ah, Bh);
                mma16816(acc[nf], Ah, Bl);
                mma16816(acc[nf], Al, Bh);
            }
        }
#pragma unroll
        for (int nf = 0; nf < 4; nf++) {
            int m = w * 16 + g;
            int h0 = (half * 4 + nf) * 8 + 2 * t;
            if (h0 < HEIGHT) {
                size_t base = ((size_t)node * 2 + (m >> 7)) * PNODE;
                float* p0 = yout + base + ((m & 127) << 6) + h0;
                *(float2*)p0 = make_float2(acc[nf][0], acc[nf][1]);
                float* p1 = yout + base + (((m + 8) & 127) << 6) + h0;
                *(float2*)p1 = make_float2(acc[nf][2], acc[nf][3]);
            }
        }
    }
}

// ---------------- setup: blk0..3 weights; blk4.. = per-node CSR ---------------
__global__ void setup_kernel(const int* __restrict__ ei, int E,
                             const float* __restrict__ conv_w,
                             const float* __restrict__ edge_w,
                             const float* __restrict__ edge_b,
                             const float* __restrict__ lng,
                             const float* __restrict__ lnb) {
    int tid = threadIdx.x;
    if (blockIdx.x >= 4) {
        __shared__ int cnt;
        __shared__ int buf[16];
        int n = blockIdx.x - 4;
        if (tid == 0) cnt = 0;
        __syncthreads();
        const int* dst = ei + E;
        for (int e = tid; e < E; e += 384) {
            if (dst[e] == n) {
                int p = atomicAdd(&cnt, 1);
                if (p < 16) buf[p] = e;
            }
        }
        __syncthreads();
        if (tid == 0) {
            int c = cnt < 16 ? cnt : 16;
            for (int a = 1; a < c; a++) {
                int v = buf[a], b = a - 1;
                while (b >= 0 && buf[b] > v) { buf[b + 1] = buf[b]; b--; }
                buf[b + 1] = v;
            }
            int cc = c < 8 ? c : 8;
            g_deg[n] = cc;
            for (int a = 0; a < cc; a++) g_nbr[n * 16 + a] = buf[a];
        }
        return;
    }
    int l = blockIdx.x;
    const float* cw = conv_w + l * (CCH * 3 * CCH);
    for (int i = tid; i < 16384; i += 384) {
        int j = i & 3, lane = (i >> 2) & 31, ks = (i >> 7) & 7, mt = i >> 10;
        int g = lane >> 2, t = lane & 3;
        int m = (mt << 4) + g + ((j & 1) << 3);
        int k = (ks << 4) + (t << 1) + ((j >> 1) << 3);
        float v0, v1;
        if (m < 128) {
            v0 = cw[m * 384 + k] - cw[m * 384 + 128 + k];
            v1 = cw[m * 384 + k + 1] - cw[m * 384 + 128 + k + 1];
        } else {
            v0 = cw[(m - 128) * 384 + 128 + k];
            v1 = cw[(m - 128) * 384 + 128 + k + 1];
        }
        float h0 = __bfloat162float(__float2bfloat16(v0));
        float h1 = __bfloat162float(__float2bfloat16(v1));
        WFh[l * 16384 + i] = pack_bf16x2(h0, h1);
        WFl[l * 16384 + i] = pack_bf16x2(v0 - h0, v1 - h1);
    }
    {
        const float* gl = lng + l * (CCH * HEIGHT);
        const float* bl = lnb + l * (CCH * HEIGHT);
        int bad = 0;
        for (int i = tid; i < CCH * HEIGHT; i += 384)
            bad |= (gl[i] != 1.f) | (bl[i] != 0.f);
        if (bad) atomicOr(&g_notok[l], 1);
    }
    if (tid < CCH) {
        int c = tid;
        const float* cw3 = cw + c * 384 + 256;
        const float* ewl = edge_w + l * (CCH * 5);
        const float* ebl = edge_b + l * CCH;
        float m0 = 0.f, m1 = 0.f, m2 = 0.f, m3 = 0.f, m4 = 0.f, m5 = 0.f;
        for (int k = 0; k < CCH; k++) {
            float w = cw3[k];
            m0 += w * ewl[k * 5 + 0];
            m1 += w * ewl[k * 5 + 1];
            m2 += w * ewl[k * 5 + 2];
            m3 += w * ewl[k * 5 + 3];
            m4 += w * ewl[k * 5 + 4];
            m5 += w * ebl[k];
        }
        float* Mp = g_M + l * (CCH * 6) + c * 6;
        Mp[0] = m0; Mp[1] = m1; Mp[2] = m2; Mp[3] = m3; Mp[4] = m4; Mp[5] = m5;
    }
}

// ---------------- G0: layer-0 GEMM, smem-resident -> buf 0 --------------------
__global__ __launch_bounds__(512, 2)
void gemm0_kernel(const float* __restrict__ x0) {
    extern __shared__ float sm[];
    float* lin = sm;
    unsigned* FH = reinterpret_cast<unsigned*>(sm + PNODE);
    unsigned* FL = FH + 4096;
    int node = blockIdx.x, tid = threadIdx.x;
    const float4* x4 = reinterpret_cast<const float4*>(x0 + (size_t)node * (CCH * HEIGHT));
    float4* lin4 = reinterpret_cast<float4*>(lin);
#pragma unroll
    for (int it = 0; it < 4; it++) {
        int i4 = tid + (it << 9);          // padded float4 index
        int c = i4 >> 4, q = i4 & 15;
        if (q != 15)                       // q==15 -> h=60..63 pad (masked in convert)
            lin4[i4] = x4[c * 15 + q];
    }
    __syncthreads();
    frag_convert(lin, FH, FL, tid);
    __syncthreads();
    mma_node(FH, FL, 0, node, tid, g_y[0]);
}

// ---------------- F_l: edge(l) [+ gemm(l+1) in-CTA], float4 everywhere --------
__global__ __launch_bounds__(512, 2)
void fused_kernel(const float* __restrict__ ea,
                  const float* __restrict__ lng,
                  const float* __restrict__ lnb,
                  const int* __restrict__ ei,
                  float* __restrict__ dout, int l) {
    extern __shared__ float sm[];
    float* lin = sm;
    unsigned* FH = reinterpret_cast<unsigned*>(sm + PNODE);
    unsigned* FL = FH + 4096;
    float* es_all = reinterpret_cast<float*>(FH);   // aliases FH (dead by MMA)
    __shared__ float red[8][32];
    __shared__ float murs[16];

    int n = blockIdx.x, tid = threadIdx.x;
    const float* ybuf = g_y[l & 1];
    const float4* yb4 = reinterpret_cast<const float4*>(ybuf);
    int deg = g_deg[n];
    int notok = g_notok[l];
    int lane = tid & 31, wid = tid >> 5;

    for (int idx = tid; idx < deg * CCH; idx += 512) {
        int j = idx >> 7, c = idx & 127;
        int e = g_nbr[n * 16 + j];
        const float* Mp = g_M + l * (CCH * 6) + c * 6;
        const float* eap = ea + e * 5;
        es_all[idx] = fmaf(Mp[0], eap[0], fmaf(Mp[1], eap[1], fmaf(Mp[2], eap[2],
                      fmaf(Mp[3], eap[3], fmaf(Mp[4], eap[4], Mp[5])))));
    }

    int yan4 = (2 * n) * (PNODE / 4);
    float4 ya4[4], acc4[4];
#pragma unroll
    for (int it = 0; it < 4; it++) {
        ya4[it] = __ldg(yb4 + yan4 + tid + (it << 9));
        acc4[it] = make_float4(0.f, 0.f, 0.f, 0.f);
    }
    __syncthreads();   // es_all visible

    if (deg == 6 && !notok) {
        // ======== FAST PATH: deg==6, trivial LN params, fully vectorized ========
        int off4[6];
#pragma unroll
        for (int j = 0; j < 6; j++)
            off4[j] = (2 * ei[g_nbr[n * 16 + j]] + 1) * (PNODE / 4);

        float s1[6], s2[6];
#pragma unroll
        for (int j = 0; j < 6; j++) { s1[j] = 0.f; s2[j] = 0.f; }
#pragma unroll
        for (int it = 0; it < 4; it++) {
            int i4 = tid + (it << 9);
            int c = i4 >> 4;
            bool val = (i4 & 15) != 15;
            float4 a = ya4[it];
#pragma unroll
            for (int j = 0; j < 6; j++) {
                float4 b = __ldg(yb4 + off4[j] + i4);
                float e = es_all[j * CCH + c];
                float v0 = a.x + b.x + e, v1 = a.y + b.y + e;
                float v2 = a.z + b.z + e, v3 = a.w + b.w + e;
                if (val) {
                    s1[j] += (v0 + v1) + (v2 + v3);
                    s2[j] += fmaf(v0, v0, v1 * v1) + fmaf(v2, v2, v3 * v3);
                }
            }
        }
#pragma unroll
        for (int j = 0; j < 6; j++) {
#pragma unroll
            for (int o = 16; o; o >>= 1) {
                s1[j] += __shfl_xor_sync(0xffffffffu, s1[j], o);
                s2[j] += __shfl_xor_sync(0xffffffffu, s2[j], o);
            }
            if (lane == 0) { red[j][wid] = s1[j]; red[j][16 + wid] = s2[j]; }
        }
        __syncthreads();
        if (wid < 6 && lane == 0) {
            float a = 0.f, b2 = 0.f;
#pragma unroll
            for (int w = 0; w < 16; w++) { a += red[wid][w]; b2 += red[wid][16 + w]; }
            float mu = a * (1.f / (float)(CCH * HEIGHT));
            murs[2 * wid] = mu;
            murs[2 * wid + 1] = rsqrtf(b2 * (1.f / (float)(CCH * HEIGHT)) - mu * mu + 1e-5f);
        }
        __syncthreads();

        // phase 2: recompute (pads produce garbage in acc; masked downstream)
#pragma unroll
        for (int j = 0; j < 6; j++) {
            float mu = murs[2 * j], rs = murs[2 * j + 1];
#pragma unroll
            for (int it = 0; it < 4; it++) {
                int i4 = tid + (it << 9);
                int c = i4 >> 4;
                float4 a = ya4[it];
                float4 b = __ldg(yb4 + off4[j] + i4);
                float e = es_all[j * CCH + c];
                acc4[it].x = fmaf(rs, fmaxf(a.x + b.x + e - mu, 0.f), acc4[it].x);
                acc4[it].y = fmaf(rs, fmaxf(a.y + b.y + e - mu, 0.f), acc4[it].y);
                acc4[it].z = fmaf(rs, fmaxf(a.z + b.z + e - mu, 0.f), acc4[it].z);
                acc4[it].w = fmaf(rs, fmaxf(a.w + b.w + e - mu, 0.f), acc4[it].w);
            }
        }
    } else {
        // ======== GENERIC PATH: per-edge, full LN, padded scalar ========
        for (int j = 0; j < deg; j++) {
            int e = g_nbr[n * 16 + j];
            int s = ei[e];
            const float4* ybj = yb4 + (2 * s + 1) * (PNODE / 4);
            const float* esj = es_all + j * CCH;

            float s1 = 0.f, s2 = 0.f;
            float4 t4[4];
#pragma unroll
            for (int it = 0; it < 4; it++) {
                int i4 = tid + (it << 9);
                int c = i4 >> 4;
                bool val = (i4 & 15) != 15;
                float4 a = ya4[it];
                float4 b = __ldg(ybj + i4);
                float ee = esj[c];
                float4 v = make_float4(a.x + b.x + ee, a.y + b.y + ee,
                                       a.z + b.z + ee, a.w + b.w + ee);
                t4[it] = v;
                if (val) {
                    s1 += (v.x + v.y) + (v.z + v.w);
                    s2 += fmaf(v.x, v.x, v.y * v.y) + fmaf(v.z, v.z, v.w * v.w);
                }
            }
#pragma unroll
            for (int o = 16; o; o >>= 1) {
                s1 += __shfl_xor_sync(0xffffffffu, s1, o);
                s2 += __shfl_xor_sync(0xffffffffu, s2, o);
            }
            if (lane == 0) { red[j][wid] = s1; red[j][16 + wid] = s2; }
            __syncthreads();
            float a = 0.f, b2 = 0.f;
#pragma unroll
            for (int w = 0; w < 16; w++) { a += red[j][w]; b2 += red[j][16 + w]; }
            float mu = a * (1.f / (float)(CCH * HEIGHT));
            float rs = rsqrtf(b2 * (1.f / (float)(CCH * HEIGHT)) - mu * mu + 1e-5f);
            if (!notok) {
#pragma unroll
                for (int it = 0; it < 4; it++) {
                    acc4[it].x = fmaf(rs, fmaxf(t4[it].x - mu, 0.f), acc4[it].x);
                    acc4[it].y = fmaf(rs, fmaxf(t4[it].y - mu, 0.f), acc4[it].y);
                    acc4[it].z = fmaf(rs, fmaxf(t4[it].z - mu, 0.f), acc4[it].z);
                    acc4[it].w = fmaf(rs, fmaxf(t4[it].w - mu, 0.f), acc4[it].w);
                }
            } else {
                const float* gl = lng + l * (CCH * HEIGHT);
                const float* bl = lnb + l * (CCH * HEIGHT);
#pragma unroll
                for (int it = 0; it < 4; it++) {
                    int i4 = tid + (it << 9);
                    int c = i4 >> 4, hb = (i4 & 15) << 2;
                    if (hb < HEIGHT) {
                        int li = c * HEIGHT + hb;
                        float o0 = (t4[it].x - mu) * rs * __ldg(gl + li)     + __ldg(bl + li);
                        float o1 = (t4[it].y - mu) * rs * __ldg(gl + li + 1) + __ldg(bl + li + 1);
                        float o2 = (t4[it].z - mu) * rs * __ldg(gl + li + 2) + __ldg(bl + li + 2);
                        float o3 = (t4[it].w - mu) * rs * __ldg(gl + li + 3) + __ldg(bl + li + 3);
                        acc4[it].x += fmaxf(o0, 0.f);
                        acc4[it].y += fmaxf(o1, 0.f);
                        acc4[it].z += fmaxf(o2, 0.f);
                        acc4[it].w += fmaxf(o3, 0.f);
                    }
                }
            }
        }
    }

    if (l == 3) {
        float* on = dout + (size_t)n * (CCH * HEIGHT);
#pragma unroll
        for (int it = 0; it < 4; it++) {
            int i4 = tid + (it << 9);
            int c = i4 >> 4, q = i4 & 15;
            if (q != 15)
                *reinterpret_cast<float4*>(on + c * HEIGHT + (q << 2)) = acc4[it];
        }
        return;
    }

    // ---- in-CTA gemm(l+1): acc -> lin (padded) -> B frags -> MMA -> buf -------
    __syncthreads();              // es_all reads complete before FH overwrite
    float4* lin4 = reinterpret_cast<float4*>(lin);
#pragma unroll
    for (int it = 0; it < 4; it++)
        lin4[tid + (it << 9)] = acc4[it];
    __syncthreads();
    frag_convert(lin, FH, FL, tid);
    __syncthreads();
    mma_node(FH, FL, l + 1, n, tid, g_y[(l + 1) & 1]);
}

// ---------------- launch -----------------------------------------------------
extern "C" void kernel_launch(void* const* d_in, const int* in_sizes, int n_in,
                              void* d_out, int out_size) {
    const float* x   = (const float*)d_in[0];
    const float* ea  = (const float*)d_in[1];
    const float* ew  = (const float*)d_in[2];
    const float* eb  = (const float*)d_in[3];
    const float* cw  = (const float*)d_in[4];
    const float* lng = (const float*)d_in[5];
    const float* lnb = (const float*)d_in[6];
    const int*   ei  = (const int*)d_in[7];
    float* out = (float*)d_out;
    int E = in_sizes[7] / 2;

    cudaFuncSetAttribute(gemm0_kernel, cudaFuncAttributeMaxDynamicSharedMemorySize, DYN_SMEM);
    cudaFuncSetAttribute(fused_kernel, cudaFuncAttributeMaxDynamicSharedMemorySize, DYN_SMEM);

    setup_kernel<<<4 + N_NODES, 384>>>(ei, E, cw, ew, eb, lng, lnb);
    gemm0_kernel<<<N_NODES, 512, DYN_SMEM>>>(x);
    for (int l = 0; l < N_LAYERS; l++)
        fused_kernel<<<N_NODES, 512, DYN_SMEM>>>(ea, lng, lnb, ei, out, l);
}